// round 7
// baseline (speedup 1.0000x reference)
#include <cuda_runtime.h>
#include <math.h>

#define C_CH   16
#define T_LEN  8192
#define F_LEN  16384
#define HF     8192
#define K_MODES 8
#define N_ITERS 19
#define ALPHA_F 2000.0f
#define NBLK   128
#define NTHR   1024

#define MODE_R 0   // all-float32: [u_out | Re(u_hat2) | Re(omega)] (2,097,312 f32) -- confirmed
#define MODE_C 1
#define MODE_M 2

// ---------------- device state ----------------
__device__ float2   g_fpos[HF * C_CH];            // [j][c_shifted]
__device__ float2   g_upos[HF * K_MODES * C_CH];  // [j][k][c_shifted]
__device__ float2   g_tw[8192];                   // (cospi, sinpi)(m/8192)
__device__ float    g_part[2][NBLK][16];
__device__ float    g_omega[(N_ITERS + 1) * K_MODES];
__device__ unsigned g_cnt;
__device__ unsigned g_gen;

// ---------------- software grid barrier ----------------
__device__ __forceinline__ void grid_barrier(unsigned target) {
    __syncthreads();
    if (threadIdx.x == 0) {
        __threadfence();
        unsigned old = atomicAdd(&g_cnt, 1u);
        if (old == NBLK - 1u) {
            g_cnt = 0u;
            asm volatile("st.global.release.gpu.b32 [%0], %1;" :: "l"(&g_gen), "r"(target) : "memory");
        } else {
            unsigned v;
            do {
                asm volatile("ld.global.acquire.gpu.b32 %0, [%1];" : "=r"(v) : "l"(&g_gen) : "memory");
            } while (v < target);
        }
    }
    __syncthreads();
}

// ---------------- fused radix-2^2 DIT FFT, twiddles from g_tw ----------------
// Bit-reversed input, natural output. Two stages per pass.
__device__ __forceinline__ void fft_smem(float2* s, int logN, float sign) {
    const int N   = 1 << logN;
    const int tid = threadIdx.x;
    const int nt  = blockDim.x;
    int st = 1;
    for (; st + 1 <= logN; st += 2) {
        const int h  = 1 << (st - 1);
        const int sh = 13 - st;               // m = jj << (13-st)
        for (int g = tid; g < (N >> 2); g += nt) {
            const int jj   = g & (h - 1);
            const int base = ((g >> (st - 1)) << (st + 1)) + jj;
            float2 a0 = s[base];
            float2 a1 = s[base + h];
            float2 a2 = s[base + 2 * h];
            float2 a3 = s[base + 3 * h];
            float2 t  = __ldg(&g_tw[jj << sh]);    // (cos, sin) of pi*jj/(2h)
            const float c2 = t.x, s2 = sign * t.y;
            const float c1 = c2 * c2 - s2 * s2;
            const float s1 = 2.0f * c2 * s2;
            float t1x = a1.x * c1 - a1.y * s1, t1y = a1.x * s1 + a1.y * c1;
            float b0x = a0.x + t1x, b0y = a0.y + t1y;
            float b1x = a0.x - t1x, b1y = a0.y - t1y;
            float t3x = a3.x * c1 - a3.y * s1, t3y = a3.x * s1 + a3.y * c1;
            float b2x = a2.x + t3x, b2y = a2.y + t3y;
            float b3x = a2.x - t3x, b3y = a2.y - t3y;
            float ux = b2x * c2 - b2y * s2, uy = b2x * s2 + b2y * c2;
            float v0x = b3x * c2 - b3y * s2, v0y = b3x * s2 + b3y * c2;
            float vx = -sign * v0y, vy = sign * v0x;
            s[base]         = make_float2(b0x + ux, b0y + uy);
            s[base + h]     = make_float2(b1x + vx, b1y + vy);
            s[base + 2 * h] = make_float2(b0x - ux, b0y - uy);
            s[base + 3 * h] = make_float2(b1x - vx, b1y - vy);
        }
        __syncthreads();
    }
    if (st <= logN) {   // leftover radix-2 stage (odd logN)
        const int half = 1 << (st - 1);
        const int sh   = 14 - st;             // m = jj << (14-st)
        for (int b = tid; b < (N >> 1); b += nt) {
            const int jj = b & (half - 1);
            const int i1 = ((b >> (st - 1)) << st) + jj;
            const int i2 = i1 + half;
            float2 t = __ldg(&g_tw[jj << sh]);
            const float cs = t.x, sn = sign * t.y;
            float2 a  = s[i1];
            float2 bb = s[i2];
            float tx = bb.x * cs - bb.y * sn;
            float ty = bb.x * sn + bb.y * cs;
            s[i1] = make_float2(a.x + tx, a.y + ty);
            s[i2] = make_float2(a.x - tx, a.y - ty);
        }
        __syncthreads();
    }
}

// ---------------- kernels ----------------
__global__ __launch_bounds__(NTHR) void init_kernel() {
    const int i = blockIdx.x * NTHR + threadIdx.x;
    if (i == 0) { g_cnt = 0u; g_gen = 0u; }
    if (i < K_MODES) g_omega[i] = 0.0625f * (float)i;
    if (i < 8192) {
        float sp, cp;
        sincospif((float)i * (1.0f / 8192.0f), &sp, &cp);
        g_tw[i] = make_float2(cp, sp);
    }
}

__device__ __forceinline__ float mirror_val(const float* sc, int i) {
    if (i < 4096)  return sc[4095 - i];
    if (i < 12288) return sc[i - 4096];
    return sc[20479 - i];
}

// Real-input FFT-16384 via complex FFT-8192 + untangle. Bins 0..8191 -> g_fpos.
__global__ __launch_bounds__(NTHR, 1) void fwd_fft_kernel(const float* __restrict__ sig) {
    extern __shared__ float2 sh[];   // 8192 float2
    const int c = blockIdx.x;
    const float* sc = sig + c * T_LEN;
    for (int n = threadIdx.x; n < HF; n += NTHR) {
        float a = mirror_val(sc, 2 * n);
        float b = mirror_val(sc, 2 * n + 1);
        sh[__brev((unsigned)n) >> 19] = make_float2(a, b);
    }
    __syncthreads();
    fft_smem(sh, 13, -1.f);
    const int cshift = (c + 8) & 15;
    for (int k = threadIdx.x; k < HF; k += NTHR) {
        float2 Zk = sh[k];
        float2 Zm = sh[(HF - k) & (HF - 1)];
        float ex = 0.5f * (Zk.x + Zm.x), ey = 0.5f * (Zk.y - Zm.y);
        float bx = 0.5f * (Zk.x - Zm.x), by = 0.5f * (Zk.y + Zm.y);
        float ox = by, oy = -bx;
        float2 t = __ldg(&g_tw[k]);
        const float cp = t.x, sp = t.y;
        float fx = ex + cp * ox + sp * oy;
        float fy = ey + cp * oy - sp * ox;
        g_fpos[k * C_CH + cshift] = make_float2(fx, fy);
    }
}

// Persistent scan: u[8] in registers, 1 grid barrier per iteration.
__global__ __launch_bounds__(NTHR, 1) void iterate_kernel() {
    const int tid  = threadIdx.x;
    const int e    = blockIdx.x * NTHR + tid;   // e = j*16 + c
    const int j    = e >> 4;
    const int lane = tid & 31;
    const int wid  = tid >> 5;
    const float fh = (float)j * (1.0f / (float)F_LEN);

    __shared__ float s_omega[K_MODES];
    __shared__ float s_wpart[32][16];
    __shared__ float s_red[16];

    if (tid < K_MODES) s_omega[tid] = 0.0625f * (float)tid;
    __syncthreads();

    const float2 fp = g_fpos[e];
    float2 u[K_MODES];
#pragma unroll
    for (int k = 0; k < K_MODES; ++k) u[k] = make_float2(0.f, 0.f);
    float2 sum = make_float2(0.f, 0.f);

    for (int it = 0; it < N_ITERS; ++it) {
        sum.x += u[K_MODES - 1].x - u[0].x;
        sum.y += u[K_MODES - 1].y - u[0].y;
        float2 prev_new = make_float2(0.f, 0.f);
        float v[16];
#pragma unroll
        for (int k = 0; k < K_MODES; ++k) {
            if (k > 0) {
                sum.x += prev_new.x - u[k].x;
                sum.y += prev_new.y - u[k].y;
            }
            float d      = fh - s_omega[k];
            float invden = 1.0f / (1.0f + ALPHA_F * d * d);
            float2 un    = make_float2((fp.x - sum.x) * invden, (fp.y - sum.y) * invden);
            u[k] = un;
            prev_new = un;
            float mag = un.x * un.x + un.y * un.y;
            v[2 * k + 0] = fh * mag;   // num
            v[2 * k + 1] = mag;        // den
        }
        // 16-value butterfly reduction across the warp (16 shfl, depth 5).
        // After: value vv lives (totalled) on lanes 2*vv and 2*vv+1.
        {
            const unsigned FM = 0xffffffffu;
#pragma unroll
            for (int i = 0; i < 8; ++i) {
                float send = (lane & 16) ? v[i] : v[i + 8];
                float recv = __shfl_xor_sync(FM, send, 16);
                v[i] = ((lane & 16) ? v[i + 8] : v[i]) + recv;
            }
#pragma unroll
            for (int i = 0; i < 4; ++i) {
                float send = (lane & 8) ? v[i] : v[i + 4];
                float recv = __shfl_xor_sync(FM, send, 8);
                v[i] = ((lane & 8) ? v[i + 4] : v[i]) + recv;
            }
#pragma unroll
            for (int i = 0; i < 2; ++i) {
                float send = (lane & 4) ? v[i] : v[i + 2];
                float recv = __shfl_xor_sync(FM, send, 4);
                v[i] = ((lane & 4) ? v[i + 2] : v[i]) + recv;
            }
            {
                float send = (lane & 2) ? v[0] : v[1];
                float recv = __shfl_xor_sync(FM, send, 2);
                v[0] = ((lane & 2) ? v[1] : v[0]) + recv;
            }
            v[0] += __shfl_xor_sync(FM, v[0], 1);
            // value index held by this lane: bits (b4,b3,b2,b1) of lane
            if ((lane & 1) == 0) s_wpart[wid][lane >> 1] = v[0];
        }
        __syncthreads();
        const int buf = it & 1;
        if (tid < 16) {
            float acc = 0.f;
#pragma unroll
            for (int w = 0; w < 32; ++w) acc += s_wpart[w][tid];
            g_part[buf][blockIdx.x][tid] = acc;
        }
        grid_barrier((unsigned)(it + 1));
        if (tid < 512) {
            const int vv = tid >> 5;
            const float* gp = &g_part[buf][0][0];
            float acc = __ldcg(gp + (lane      ) * 16 + vv)
                      + __ldcg(gp + (lane +  32) * 16 + vv)
                      + __ldcg(gp + (lane +  64) * 16 + vv)
                      + __ldcg(gp + (lane +  96) * 16 + vv);
#pragma unroll
            for (int o = 16; o; o >>= 1) acc += __shfl_down_sync(0xffffffffu, acc, o);
            if (lane == 0) s_red[vv] = acc;
        }
        __syncthreads();
        if (tid < K_MODES) {
            float om = s_red[2 * tid] / s_red[2 * tid + 1];
            s_omega[tid] = om;
            if (blockIdx.x == 0) g_omega[(it + 1) * K_MODES + tid] = om;
        }
        __syncthreads();
    }

    const int c = e & 15;
#pragma unroll
    for (int k = 0; k < K_MODES; ++k)
        g_upos[(j * K_MODES + k) * C_CH + c] = u[k];
}

// Per (k,c_shifted): irfft-16384 via complex ifft-8192 (prep twiddle), slice
// -> u_out; then rfft-8192 via complex fft-4096 + untangle -> u_hat2.
__global__ __launch_bounds__(NTHR, 1) void recon_kernel(float* __restrict__ dout, int mode,
                                                        long long limf) {
    extern __shared__ float2 sh[];
    float2* sh1 = sh;            // 8192 float2
    float2* sh2 = sh + 8192;     // 4096 float2
    float*  rey = (float*)sh;            // overlays sh1 (dead by then)
    float*  imy = ((float*)sh) + 4608;
    const int b   = blockIdx.x;
    const int k   = b >> 4;
    const int c   = b & 15;
    const int tid = threadIdx.x;
    const long long lim2 = limf >> 1;

    // prep: Zc[q] = P + i*Q ; P=H[q]+H[q+M], Q=e^{+i*pi*q/8192}(H[q]-H[q+M])
    for (int q = tid; q < HF; q += NTHR) {
        float2 Hk, HM;
        if (q == 0) {
            float2 p0 = g_upos[(0 * K_MODES + k) * C_CH + c];
            float2 pL = g_upos[((HF - 1) * K_MODES + k) * C_CH + c];
            Hk = make_float2(p0.x, 0.f);
            HM = make_float2(pL.x, 0.f);
        } else {
            Hk = g_upos[(q * K_MODES + k) * C_CH + c];
            float2 pm = g_upos[((HF - q) * K_MODES + k) * C_CH + c];
            HM = make_float2(pm.x, -pm.y);
        }
        float px = Hk.x + HM.x, py = Hk.y + HM.y;
        float dx = Hk.x - HM.x, dy = Hk.y - HM.y;
        float2 t = __ldg(&g_tw[q]);
        const float cp = t.x, sp = t.y;
        float qx = cp * dx - sp * dy, qy = cp * dy + sp * dx;
        sh1[__brev((unsigned)q) >> 19] = make_float2(px - qy, py + qx);
    }
    __syncthreads();
    fft_smem(sh1, 13, +1.f);

    const float invN = 1.0f / (float)F_LEN;
    const int cs = (c + 8) & 15;
    for (int n = tid; n < 4096; n += NTHR) {
        float2 z = sh1[2048 + n];
        float w0 = z.x * invN, w1 = z.y * invN;
        long long i0 = (long long)(k * T_LEN + 2 * n) * C_CH + cs;
        long long i1 = i0 + C_CH;
        if (mode == MODE_C) {
            float2* o = (float2*)dout;
            if (i0 < lim2) o[i0] = make_float2(w0, 0.f);
            if (i1 < lim2) o[i1] = make_float2(w1, 0.f);
        } else {
            if (i0 < limf) dout[i0] = w0;
            if (i1 < limf) dout[i1] = w1;
        }
        sh2[__brev((unsigned)n) >> 20] = make_float2(w0, w1);
    }
    __syncthreads();
    fft_smem(sh2, 12, -1.f);

    // untangle rfft: Y[q]=E+e^{-i*pi*q/4096}O, q=0..4095; Y[4096]=ReZZ0-ImZZ0
    for (int q = tid; q < 4096; q += NTHR) {
        float2 Zk = sh2[q];
        float2 Zm = sh2[(4096 - q) & 4095];
        float ex = 0.5f * (Zk.x + Zm.x), ey = 0.5f * (Zk.y - Zm.y);
        float bx = 0.5f * (Zk.x - Zm.x), by = 0.5f * (Zk.y + Zm.y);
        float ox = by, oy = -bx;
        float2 t = __ldg(&g_tw[2 * q]);
        const float cp = t.x, sp = t.y;
        rey[q] = ex + cp * ox + sp * oy;
        imy[q] = ey + cp * oy - sp * ox;
        if (q == 0) { rey[4096] = Zk.x - Zk.y; imy[4096] = 0.f; }
    }
    __syncthreads();

    // u_hat2[t][k][c] = conj(Y[t^4096]); real w => Y[8192-b]=conj(Y[b])
    if (mode == MODE_R) {
        const long long base = (long long)T_LEN * K_MODES * C_CH;
        for (int t = tid; t < T_LEN; t += NTHR) {
            int bb = t ^ 4096;
            int rb = (bb <= 4096) ? bb : 8192 - bb;
            long long idx = base + ((long long)t * K_MODES + k) * C_CH + c;
            if (idx < limf) dout[idx] = rey[rb];
        }
    } else {
        const long long base2 = (mode == MODE_M)
            ? (long long)(T_LEN * K_MODES * C_CH / 2)
            : (long long)(T_LEN * K_MODES * C_CH);
        float2* o = (float2*)dout;
        for (int t = tid; t < T_LEN; t += NTHR) {
            int bb = t ^ 4096;
            float re, im;
            if (bb <= 4096) { re = rey[bb];        im = -imy[bb]; }
            else            { re = rey[8192 - bb]; im =  imy[8192 - bb]; }
            long long idx = base2 + ((long long)t * K_MODES + k) * C_CH + c;
            if (idx < lim2) o[idx] = make_float2(re, im);
        }
    }
}

__global__ void omega_out_kernel(float* __restrict__ dout, int mode, long long limf) {
    int i = threadIdx.x;
    if (i >= (N_ITERS + 1) * K_MODES) return;
    if (mode == MODE_R) {
        long long idx = 2097152LL + i;
        if (idx < limf) dout[idx] = g_omega[i];
    } else {
        long long base2 = (mode == MODE_M) ? 1572864LL : 2097152LL;
        long long idx = base2 + i;
        if (idx < (limf >> 1)) ((float2*)dout)[idx] = make_float2(g_omega[i], 0.f);
    }
}

// ---------------- launch ----------------
extern "C" void kernel_launch(void* const* d_in, const int* in_sizes, int n_in,
                              void* d_out, int out_size) {
    const float* sig = (const float*)d_in[0];

    int mode;
    if (out_size == 4194624)      mode = MODE_C;
    else if (out_size == 3146048) mode = MODE_M;
    else                          mode = MODE_R;
    const long long limf = (long long)out_size;

    cudaFuncSetAttribute(fwd_fft_kernel, cudaFuncAttributeMaxDynamicSharedMemorySize, 65536);
    cudaFuncSetAttribute(recon_kernel,   cudaFuncAttributeMaxDynamicSharedMemorySize, 98304);

    init_kernel<<<8, NTHR>>>();
    fwd_fft_kernel<<<C_CH, NTHR, 65536>>>(sig);
    iterate_kernel<<<NBLK, NTHR>>>();
    recon_kernel<<<NBLK, NTHR, 98304>>>((float*)d_out, mode, limf);
    omega_out_kernel<<<1, 192>>>((float*)d_out, mode, limf);
}

// round 8
// speedup vs baseline: 1.1963x; 1.1963x over previous
#include <cuda_runtime.h>
#include <math.h>

#define C_CH   16
#define T_LEN  8192
#define F_LEN  16384
#define HF     8192
#define K_MODES 8
#define N_ITERS 19
#define ALPHA_F 2000.0f
#define NBLK   128
#define NTHR   1024

#define MODE_R 0   // all-float32: [u_out | Re(u_hat2) | Re(omega)] (2,097,312 f32) -- confirmed
#define MODE_C 1
#define MODE_M 2

// padded smem index: 1 extra float2 per 16 -> breaks power-of-2 stride conflicts
#define PHI(i) ((i) + ((i) >> 4))

// ---------------- device state ----------------
__device__ float2   g_fpos[HF * C_CH];            // [j][c_shifted]
__device__ float2   g_upos[HF * K_MODES * C_CH];  // [j][k][c_shifted]
__device__ float    g_part[2][NBLK][16];
__device__ float    g_omega[(N_ITERS + 1) * K_MODES];
__device__ unsigned g_cnt;
__device__ unsigned g_gen;

// ---------------- software grid barrier ----------------
__device__ __forceinline__ void grid_barrier(unsigned target) {
    __syncthreads();
    if (threadIdx.x == 0) {
        __threadfence();
        unsigned old = atomicAdd(&g_cnt, 1u);
        if (old == NBLK - 1u) {
            g_cnt = 0u;
            asm volatile("st.global.release.gpu.b32 [%0], %1;" :: "l"(&g_gen), "r"(target) : "memory");
        } else {
            unsigned v;
            do {
                asm volatile("ld.global.acquire.gpu.b32 %0, [%1];" : "=r"(v) : "l"(&g_gen) : "memory");
            } while (v < target);
        }
    }
    __syncthreads();
}

// ---------------- complex helpers ----------------
__device__ __forceinline__ float2 cmulf(float2 a, float c, float s) {
    return make_float2(a.x * c - a.y * s, a.x * s + a.y * c);
}
__device__ __forceinline__ float2 cadd(float2 a, float2 b) { return make_float2(a.x + b.x, a.y + b.y); }
__device__ __forceinline__ float2 csub(float2 a, float2 b) { return make_float2(a.x - b.x, a.y - b.y); }

// ---------------- fused radix-2^3 DIT pass (stages st, st+1, st+2) ----------
// s is PHI-padded; bit-reversed input convention; one sincospif per 8 elems.
__device__ __forceinline__ void r8_pass(float2* s, int N8, int st, float inv4h, float sign) {
    const int h = 1 << (st - 1);
    for (int g = threadIdx.x; g < N8; g += NTHR) {
        const int jj   = g & (h - 1);
        const int base = ((g >> (st - 1)) << (st + 2)) + jj;
        float2 x0 = s[PHI(base)];
        float2 x1 = s[PHI(base + h)];
        float2 x2 = s[PHI(base + 2 * h)];
        float2 x3 = s[PHI(base + 3 * h)];
        float2 x4 = s[PHI(base + 4 * h)];
        float2 x5 = s[PHI(base + 5 * h)];
        float2 x6 = s[PHI(base + 6 * h)];
        float2 x7 = s[PHI(base + 7 * h)];
        float sw, cw; sincospif((float)jj * inv4h, &sw, &cw);
        sw *= sign;                       // w = exp(sign*i*pi*jj/(4h)), folded
        const float c2 = cw * cw - sw * sw, s2 = 2.f * cw * sw;   // w^2
        const float c1 = c2 * c2 - s2 * s2, s1 = 2.f * c2 * s2;   // w^4
        // stage st (twiddle w1)
        float2 t1 = cmulf(x1, c1, s1);
        float2 y0 = cadd(x0, t1), y1 = csub(x0, t1);
        float2 t3 = cmulf(x3, c1, s1);
        float2 y2 = cadd(x2, t3), y3 = csub(x2, t3);
        float2 t5 = cmulf(x5, c1, s1);
        float2 y4 = cadd(x4, t5), y5 = csub(x4, t5);
        float2 t7 = cmulf(x7, c1, s1);
        float2 y6 = cadd(x6, t7), y7 = csub(x6, t7);
        // stage st+1 (w2 ; sign*i*w2)
        const float fx = -sign * s2, fy = sign * c2;
        float2 u2 = cmulf(y2, c2, s2);
        float2 z0 = cadd(y0, u2), z2 = csub(y0, u2);
        float2 u3 = cmulf(y3, fx, fy);
        float2 z1 = cadd(y1, u3), z3 = csub(y1, u3);
        float2 u6 = cmulf(y6, c2, s2);
        float2 z4 = cadd(y4, u6), z6 = csub(y4, u6);
        float2 u7 = cmulf(y7, fx, fy);
        float2 z5 = cadd(y5, u7), z7 = csub(y5, u7);
        // stage st+2 (w * e_t, e_t = exp(sign*i*pi*t/4))
        const float C45 = 0.70710678118654752440f;
        float2 v4 = cmulf(z4, cw, sw);
        float2 v5 = cmulf(z5, C45 * (cw - sign * sw), C45 * (sign * cw + sw));
        float2 v6 = cmulf(z6, -sign * sw, sign * cw);
        float2 v7 = cmulf(z7, C45 * (-cw - sign * sw), C45 * (sign * cw - sw));
        s[PHI(base)]         = cadd(z0, v4);
        s[PHI(base + 4 * h)] = csub(z0, v4);
        s[PHI(base + h)]     = cadd(z1, v5);
        s[PHI(base + 5 * h)] = csub(z1, v5);
        s[PHI(base + 2 * h)] = cadd(z2, v6);
        s[PHI(base + 6 * h)] = csub(z2, v6);
        s[PHI(base + 3 * h)] = cadd(z3, v7);
        s[PHI(base + 7 * h)] = csub(z3, v7);
    }
    __syncthreads();
}

// ---------------- kernels ----------------
__global__ void init_kernel() {
    if (threadIdx.x == 0) { g_cnt = 0u; g_gen = 0u; }
    if (threadIdx.x < K_MODES)
        g_omega[threadIdx.x] = 0.0625f * (float)threadIdx.x;
}

__device__ __forceinline__ float mirror_val(const float* sc, int i) {
    if (i < 4096)  return sc[4095 - i];
    if (i < 12288) return sc[i - 4096];
    return sc[20479 - i];
}

// Real-input FFT-16384 via complex FFT-8192 (pack even/odd) + untangle.
// fft8192 = fused load+stage1 (positions 2b,2b+1 <- inputs r12(b), r12(b)+4096),
// then radix-8 passes at st=2,5,8,11.
__global__ __launch_bounds__(NTHR, 1) void fwd_fft_kernel(const float* __restrict__ sig) {
    extern __shared__ float2 sh[];   // PHI-padded, 8704 float2
    const int c = blockIdx.x;
    const float* sc = sig + c * T_LEN;
    for (int b = threadIdx.x; b < 4096; b += NTHR) {
        const int q0 = __brev((unsigned)b) >> 20;   // r12(b)
        const int q1 = q0 + 4096;
        float2 A = make_float2(mirror_val(sc, 2 * q0), mirror_val(sc, 2 * q0 + 1));
        float2 B = make_float2(mirror_val(sc, 2 * q1), mirror_val(sc, 2 * q1 + 1));
        sh[PHI(2 * b)]     = cadd(A, B);
        sh[PHI(2 * b + 1)] = csub(A, B);
    }
    __syncthreads();
    r8_pass(sh, 1024, 2,  1.f / 8.f,    -1.f);
    r8_pass(sh, 1024, 5,  1.f / 64.f,   -1.f);
    r8_pass(sh, 1024, 8,  1.f / 512.f,  -1.f);
    r8_pass(sh, 1024, 11, 1.f / 4096.f, -1.f);
    const int cshift = (c + 8) & 15;
    for (int k = threadIdx.x; k < HF; k += NTHR) {
        float2 Zk = sh[PHI(k)];
        float2 Zm = sh[PHI((HF - k) & (HF - 1))];
        float ex = 0.5f * (Zk.x + Zm.x), ey = 0.5f * (Zk.y - Zm.y);
        float bx = 0.5f * (Zk.x - Zm.x), by = 0.5f * (Zk.y + Zm.y);
        float ox = by, oy = -bx;
        float sp, cp; sincospif((float)k * (1.0f / (float)HF), &sp, &cp);
        float fxv = ex + cp * ox + sp * oy;
        float fyv = ey + cp * oy - sp * ox;
        g_fpos[k * C_CH + cshift] = make_float2(fxv, fyv);
    }
}

// Persistent scan (exact R6 code path): u[8] in registers, 1 grid barrier/iter.
__global__ __launch_bounds__(NTHR, 1) void iterate_kernel() {
    const int tid  = threadIdx.x;
    const int e    = blockIdx.x * NTHR + tid;   // e = j*16 + c
    const int j    = e >> 4;
    const int lane = tid & 31;
    const int wid  = tid >> 5;
    const float fh = (float)j * (1.0f / (float)F_LEN);

    __shared__ float s_omega[K_MODES];
    __shared__ float s_wpart[32][16];
    __shared__ float s_red[16];

    if (tid < K_MODES) s_omega[tid] = 0.0625f * (float)tid;
    __syncthreads();

    const float2 fp = g_fpos[e];
    float2 u[K_MODES];
#pragma unroll
    for (int k = 0; k < K_MODES; ++k) u[k] = make_float2(0.f, 0.f);
    float2 sum = make_float2(0.f, 0.f);

    for (int it = 0; it < N_ITERS; ++it) {
        sum.x += u[K_MODES - 1].x - u[0].x;
        sum.y += u[K_MODES - 1].y - u[0].y;
        float2 prev_new = make_float2(0.f, 0.f);
#pragma unroll
        for (int k = 0; k < K_MODES; ++k) {
            if (k > 0) {
                sum.x += prev_new.x - u[k].x;
                sum.y += prev_new.y - u[k].y;
            }
            float d      = fh - s_omega[k];
            float invden = 1.0f / (1.0f + ALPHA_F * d * d);
            float2 un    = make_float2((fp.x - sum.x) * invden, (fp.y - sum.y) * invden);
            u[k] = un;
            prev_new = un;
            float mag = un.x * un.x + un.y * un.y;
            float num = fh * mag;
#pragma unroll
            for (int o = 16; o; o >>= 1) {
                mag += __shfl_down_sync(0xffffffffu, mag, o);
                num += __shfl_down_sync(0xffffffffu, num, o);
            }
            if (lane == 0) {
                s_wpart[wid][k * 2 + 0] = num;
                s_wpart[wid][k * 2 + 1] = mag;
            }
        }
        __syncthreads();
        const int buf = it & 1;
        if (tid < 16) {
            float acc = 0.f;
#pragma unroll
            for (int w = 0; w < 32; ++w) acc += s_wpart[w][tid];
            g_part[buf][blockIdx.x][tid] = acc;
        }
        grid_barrier((unsigned)(it + 1));
        if (tid < 512) {
            const int v = tid >> 5;
            const float* gp = &g_part[buf][0][0];
            float acc = __ldcg(gp + (lane      ) * 16 + v)
                      + __ldcg(gp + (lane +  32) * 16 + v)
                      + __ldcg(gp + (lane +  64) * 16 + v)
                      + __ldcg(gp + (lane +  96) * 16 + v);
#pragma unroll
            for (int o = 16; o; o >>= 1) acc += __shfl_down_sync(0xffffffffu, acc, o);
            if (lane == 0) s_red[v] = acc;
        }
        __syncthreads();
        if (tid < K_MODES) {
            float om = s_red[2 * tid] / s_red[2 * tid + 1];
            s_omega[tid] = om;
            if (blockIdx.x == 0) g_omega[(it + 1) * K_MODES + tid] = om;
        }
        __syncthreads();
    }

    const int c = e & 15;
#pragma unroll
    for (int k = 0; k < K_MODES; ++k)
        g_upos[(j * K_MODES + k) * C_CH + c] = u[k];
}

// conceptual prep value Zc[q] (q in [0,8192)) for column (k,c)
__device__ __forceinline__ float2 prep_val(int q, int k, int c) {
    float2 Hk, HM;
    if (q == 0) {
        float2 p0 = g_upos[(0 * K_MODES + k) * C_CH + c];
        float2 pL = g_upos[((HF - 1) * K_MODES + k) * C_CH + c];
        Hk = make_float2(p0.x, 0.f);
        HM = make_float2(pL.x, 0.f);
    } else {
        Hk = g_upos[(q * K_MODES + k) * C_CH + c];
        float2 pm = g_upos[((HF - q) * K_MODES + k) * C_CH + c];
        HM = make_float2(pm.x, -pm.y);
    }
    float px = Hk.x + HM.x, py = Hk.y + HM.y;
    float dx = Hk.x - HM.x, dy = Hk.y - HM.y;
    float sp, cp; sincospif((float)q * (1.0f / (float)HF), &sp, &cp);
    float qx = cp * dx - sp * dy, qy = cp * dy + sp * dx;
    return make_float2(px - qy, py + qx);
}

// Per (k,c_shifted): irfft-16384 via complex ifft-8192, slice -> u_out;
// then rfft-8192 via complex fft-4096 + untangle -> u_hat2.
__global__ __launch_bounds__(NTHR, 1) void recon_kernel(float* __restrict__ dout, int mode,
                                                        long long limf) {
    extern __shared__ float2 sh[];
    float2* sh1 = sh;             // PHI-padded 8704 float2
    float2* sh2 = sh + 8704;      // PHI-padded 4352 float2
    float*  rey = (float*)sh;     // overlays sh1 (dead by then)
    float*  imy = ((float*)sh) + 4608;
    const int b   = blockIdx.x;
    const int k   = b >> 4;
    const int c   = b & 15;
    const int tid = threadIdx.x;
    const long long lim2 = limf >> 1;

    // fused prep + stage 1 of ifft8192
    for (int bb = tid; bb < 4096; bb += NTHR) {
        const int q0 = __brev((unsigned)bb) >> 20;
        float2 A = prep_val(q0, k, c);
        float2 B = prep_val(q0 + 4096, k, c);
        sh1[PHI(2 * bb)]     = cadd(A, B);
        sh1[PHI(2 * bb + 1)] = csub(A, B);
    }
    __syncthreads();
    r8_pass(sh1, 1024, 2,  1.f / 8.f,    +1.f);
    r8_pass(sh1, 1024, 5,  1.f / 64.f,   +1.f);
    r8_pass(sh1, 1024, 8,  1.f / 512.f,  +1.f);
    r8_pass(sh1, 1024, 11, 1.f / 4096.f, +1.f);

    // u_out (t = 2n, 2n+1 from z[2048+n]) + pack fft4096 input (bit-reversed)
    const float invN = 1.0f / (float)F_LEN;
    const int cs = (c + 8) & 15;
    for (int n = tid; n < 4096; n += NTHR) {
        float2 z = sh1[PHI(2048 + n)];
        float w0 = z.x * invN, w1 = z.y * invN;
        long long i0 = (long long)(k * T_LEN + 2 * n) * C_CH + cs;
        long long i1 = i0 + C_CH;
        if (mode == MODE_C) {
            float2* o = (float2*)dout;
            if (i0 < lim2) o[i0] = make_float2(w0, 0.f);
            if (i1 < lim2) o[i1] = make_float2(w1, 0.f);
        } else {
            if (i0 < limf) dout[i0] = w0;
            if (i1 < limf) dout[i1] = w1;
        }
        sh2[PHI(__brev((unsigned)n) >> 20)] = make_float2(w0, w1);
    }
    __syncthreads();
    r8_pass(sh2, 512, 1,  1.f / 4.f,    -1.f);
    r8_pass(sh2, 512, 4,  1.f / 32.f,   -1.f);
    r8_pass(sh2, 512, 7,  1.f / 256.f,  -1.f);
    r8_pass(sh2, 512, 10, 1.f / 2048.f, -1.f);

    // untangle rfft: Y[q]=E+e^{-i*pi*q/4096}O, q=0..4095; Y[4096]=ReZZ0-ImZZ0
    for (int q = tid; q < 4096; q += NTHR) {
        float2 Zk = sh2[PHI(q)];
        float2 Zm = sh2[PHI((4096 - q) & 4095)];
        float ex = 0.5f * (Zk.x + Zm.x), ey = 0.5f * (Zk.y - Zm.y);
        float bx = 0.5f * (Zk.x - Zm.x), by = 0.5f * (Zk.y + Zm.y);
        float ox = by, oy = -bx;
        float sp, cp; sincospif((float)q * (1.0f / 4096.0f), &sp, &cp);
        rey[q] = ex + cp * ox + sp * oy;
        imy[q] = ey + cp * oy - sp * ox;
        if (q == 0) { rey[4096] = Zk.x - Zk.y; imy[4096] = 0.f; }
    }
    __syncthreads();

    // u_hat2[t][k][c] = conj(Y[t^4096]); real input => Y[8192-b]=conj(Y[b])
    if (mode == MODE_R) {
        const long long base = (long long)T_LEN * K_MODES * C_CH;
        for (int t = tid; t < T_LEN; t += NTHR) {
            int bb2 = t ^ 4096;
            int rb = (bb2 <= 4096) ? bb2 : 8192 - bb2;
            long long idx = base + ((long long)t * K_MODES + k) * C_CH + c;
            if (idx < limf) dout[idx] = rey[rb];
        }
    } else {
        const long long base2 = (mode == MODE_M)
            ? (long long)(T_LEN * K_MODES * C_CH / 2)
            : (long long)(T_LEN * K_MODES * C_CH);
        float2* o = (float2*)dout;
        for (int t = tid; t < T_LEN; t += NTHR) {
            int bb2 = t ^ 4096;
            float re, im;
            if (bb2 <= 4096) { re = rey[bb2];        im = -imy[bb2]; }
            else             { re = rey[8192 - bb2]; im =  imy[8192 - bb2]; }
            long long idx = base2 + ((long long)t * K_MODES + k) * C_CH + c;
            if (idx < lim2) o[idx] = make_float2(re, im);
        }
    }
}

__global__ void omega_out_kernel(float* __restrict__ dout, int mode, long long limf) {
    int i = threadIdx.x;
    if (i >= (N_ITERS + 1) * K_MODES) return;
    if (mode == MODE_R) {
        long long idx = 2097152LL + i;
        if (idx < limf) dout[idx] = g_omega[i];
    } else {
        long long base2 = (mode == MODE_M) ? 1572864LL : 2097152LL;
        long long idx = base2 + i;
        if (idx < (limf >> 1)) ((float2*)dout)[idx] = make_float2(g_omega[i], 0.f);
    }
}

// ---------------- launch ----------------
extern "C" void kernel_launch(void* const* d_in, const int* in_sizes, int n_in,
                              void* d_out, int out_size) {
    const float* sig = (const float*)d_in[0];

    int mode;
    if (out_size == 4194624)      mode = MODE_C;
    else if (out_size == 3146048) mode = MODE_M;
    else                          mode = MODE_R;
    const long long limf = (long long)out_size;

    const int FWD_SMEM = 8704 * 8;            // 69632 B
    const int REC_SMEM = (8704 + 4352) * 8;   // 104448 B
    cudaFuncSetAttribute(fwd_fft_kernel, cudaFuncAttributeMaxDynamicSharedMemorySize, FWD_SMEM);
    cudaFuncSetAttribute(recon_kernel,   cudaFuncAttributeMaxDynamicSharedMemorySize, REC_SMEM);

    init_kernel<<<1, 32>>>();
    fwd_fft_kernel<<<C_CH, NTHR, FWD_SMEM>>>(sig);
    iterate_kernel<<<NBLK, NTHR>>>();
    recon_kernel<<<NBLK, NTHR, REC_SMEM>>>((float*)d_out, mode, limf);
    omega_out_kernel<<<1, 192>>>((float*)d_out, mode, limf);
}

// round 9
// speedup vs baseline: 1.2714x; 1.0627x over previous
#include <cuda_runtime.h>
#include <math.h>

#define C_CH   16
#define T_LEN  8192
#define F_LEN  16384
#define HF     8192
#define K_MODES 8
#define N_ITERS 19
#define ALPHA_F 2000.0f
#define NBLK   128
#define NTHR   1024

#define MODE_R 0   // all-float32: [u_out | Re(u_hat2) | Re(omega)] (2,097,312 f32) -- confirmed
#define MODE_C 1
#define MODE_M 2

// padded smem index: 1 extra float2 per 16 -> breaks power-of-2 stride conflicts
#define PHI(i) ((i) + ((i) >> 4))

// ---------------- device state ----------------
__device__ float2   g_fpos[HF * C_CH];            // [j][c_shifted]
__device__ float2   g_upos[HF * K_MODES * C_CH];  // [j][k][c_shifted]
__device__ float    g_part[NBLK][16];             // per-block partials (single buffer)
__device__ float    g_omega[(N_ITERS + 1) * K_MODES];
__device__ unsigned g_flags[NBLK];
__device__ unsigned g_gen;

// ---------------- complex helpers ----------------
__device__ __forceinline__ float2 cmulf(float2 a, float c, float s) {
    return make_float2(a.x * c - a.y * s, a.x * s + a.y * c);
}
__device__ __forceinline__ float2 cadd(float2 a, float2 b) { return make_float2(a.x + b.x, a.y + b.y); }
__device__ __forceinline__ float2 csub(float2 a, float2 b) { return make_float2(a.x - b.x, a.y - b.y); }

// ---------------- fused radix-2^3 DIT pass (stages st, st+1, st+2) ----------
__device__ __forceinline__ void r8_pass(float2* s, int N8, int st, float inv4h, float sign) {
    const int h = 1 << (st - 1);
    for (int g = threadIdx.x; g < N8; g += NTHR) {
        const int jj   = g & (h - 1);
        const int base = ((g >> (st - 1)) << (st + 2)) + jj;
        float2 x0 = s[PHI(base)];
        float2 x1 = s[PHI(base + h)];
        float2 x2 = s[PHI(base + 2 * h)];
        float2 x3 = s[PHI(base + 3 * h)];
        float2 x4 = s[PHI(base + 4 * h)];
        float2 x5 = s[PHI(base + 5 * h)];
        float2 x6 = s[PHI(base + 6 * h)];
        float2 x7 = s[PHI(base + 7 * h)];
        float sw, cw; sincospif((float)jj * inv4h, &sw, &cw);
        sw *= sign;
        const float c2 = cw * cw - sw * sw, s2 = 2.f * cw * sw;   // w^2
        const float c1 = c2 * c2 - s2 * s2, s1 = 2.f * c2 * s2;   // w^4
        float2 t1 = cmulf(x1, c1, s1);
        float2 y0 = cadd(x0, t1), y1 = csub(x0, t1);
        float2 t3 = cmulf(x3, c1, s1);
        float2 y2 = cadd(x2, t3), y3 = csub(x2, t3);
        float2 t5 = cmulf(x5, c1, s1);
        float2 y4 = cadd(x4, t5), y5 = csub(x4, t5);
        float2 t7 = cmulf(x7, c1, s1);
        float2 y6 = cadd(x6, t7), y7 = csub(x6, t7);
        const float fx = -sign * s2, fy = sign * c2;
        float2 u2 = cmulf(y2, c2, s2);
        float2 z0 = cadd(y0, u2), z2 = csub(y0, u2);
        float2 u3 = cmulf(y3, fx, fy);
        float2 z1 = cadd(y1, u3), z3 = csub(y1, u3);
        float2 u6 = cmulf(y6, c2, s2);
        float2 z4 = cadd(y4, u6), z6 = csub(y4, u6);
        float2 u7 = cmulf(y7, fx, fy);
        float2 z5 = cadd(y5, u7), z7 = csub(y5, u7);
        const float C45 = 0.70710678118654752440f;
        float2 v4 = cmulf(z4, cw, sw);
        float2 v5 = cmulf(z5, C45 * (cw - sign * sw), C45 * (sign * cw + sw));
        float2 v6 = cmulf(z6, -sign * sw, sign * cw);
        float2 v7 = cmulf(z7, C45 * (-cw - sign * sw), C45 * (sign * cw - sw));
        s[PHI(base)]         = cadd(z0, v4);
        s[PHI(base + 4 * h)] = csub(z0, v4);
        s[PHI(base + h)]     = cadd(z1, v5);
        s[PHI(base + 5 * h)] = csub(z1, v5);
        s[PHI(base + 2 * h)] = cadd(z2, v6);
        s[PHI(base + 6 * h)] = csub(z2, v6);
        s[PHI(base + 3 * h)] = cadd(z3, v7);
        s[PHI(base + 7 * h)] = csub(z3, v7);
    }
    __syncthreads();
}

// ---------------- kernels ----------------
__global__ void init_kernel() {
    const int i = threadIdx.x;
    if (i == 0) g_gen = 0u;
    if (i < NBLK) g_flags[i] = 0u;
    if (i < K_MODES) g_omega[i] = 0.0625f * (float)i;
}

__device__ __forceinline__ float mirror_val(const float* sc, int i) {
    if (i < 4096)  return sc[4095 - i];
    if (i < 12288) return sc[i - 4096];
    return sc[20479 - i];
}

// Real-input FFT-16384 via complex FFT-8192 (pack even/odd) + untangle.
__global__ __launch_bounds__(NTHR, 1) void fwd_fft_kernel(const float* __restrict__ sig) {
    extern __shared__ float2 sh[];   // PHI-padded, 8704 float2
    const int c = blockIdx.x;
    const float* sc = sig + c * T_LEN;
    for (int b = threadIdx.x; b < 4096; b += NTHR) {
        const int q0 = __brev((unsigned)b) >> 20;   // r12(b)
        const int q1 = q0 + 4096;
        float2 A = make_float2(mirror_val(sc, 2 * q0), mirror_val(sc, 2 * q0 + 1));
        float2 B = make_float2(mirror_val(sc, 2 * q1), mirror_val(sc, 2 * q1 + 1));
        sh[PHI(2 * b)]     = cadd(A, B);
        sh[PHI(2 * b + 1)] = csub(A, B);
    }
    __syncthreads();
    r8_pass(sh, 1024, 2,  1.f / 8.f,    -1.f);
    r8_pass(sh, 1024, 5,  1.f / 64.f,   -1.f);
    r8_pass(sh, 1024, 8,  1.f / 512.f,  -1.f);
    r8_pass(sh, 1024, 11, 1.f / 4096.f, -1.f);
    const int cshift = (c + 8) & 15;
    for (int k = threadIdx.x; k < HF; k += NTHR) {
        float2 Zk = sh[PHI(k)];
        float2 Zm = sh[PHI((HF - k) & (HF - 1))];
        float ex = 0.5f * (Zk.x + Zm.x), ey = 0.5f * (Zk.y - Zm.y);
        float bx = 0.5f * (Zk.x - Zm.x), by = 0.5f * (Zk.y + Zm.y);
        float ox = by, oy = -bx;
        float sp, cp; sincospif((float)k * (1.0f / (float)HF), &sp, &cp);
        float fxv = ex + cp * ox + sp * oy;
        float fyv = ey + cp * oy - sp * ox;
        g_fpos[k * C_CH + cshift] = make_float2(fxv, fyv);
    }
}

// Persistent scan: u[8] in registers; flag-based barrier, block0-only reduce.
__global__ __launch_bounds__(NTHR, 1) void iterate_kernel() {
    const int tid  = threadIdx.x;
    const int e    = blockIdx.x * NTHR + tid;   // e = j*16 + c
    const int j    = e >> 4;
    const int lane = tid & 31;
    const int wid  = tid >> 5;
    const float fh = (float)j * (1.0f / (float)F_LEN);

    __shared__ float s_omega[K_MODES];
    __shared__ float s_wpart[32][16];
    __shared__ float s_red[16];

    if (tid < K_MODES) s_omega[tid] = 0.0625f * (float)tid;
    __syncthreads();

    const float2 fp = g_fpos[e];
    float2 u[K_MODES];
#pragma unroll
    for (int k = 0; k < K_MODES; ++k) u[k] = make_float2(0.f, 0.f);
    float2 sum = make_float2(0.f, 0.f);

    for (int it = 0; it < N_ITERS; ++it) {
        const unsigned target = (unsigned)(it + 1);
        sum.x += u[K_MODES - 1].x - u[0].x;
        sum.y += u[K_MODES - 1].y - u[0].y;
        float2 prev_new = make_float2(0.f, 0.f);
        float v[16];
#pragma unroll
        for (int k = 0; k < K_MODES; ++k) {
            if (k > 0) {
                sum.x += prev_new.x - u[k].x;
                sum.y += prev_new.y - u[k].y;
            }
            float d      = fh - s_omega[k];
            float invden = 1.0f / (1.0f + ALPHA_F * d * d);
            float2 un    = make_float2((fp.x - sum.x) * invden, (fp.y - sum.y) * invden);
            u[k] = un;
            prev_new = un;
            float mag = un.x * un.x + un.y * un.y;
            v[2 * k + 0] = fh * mag;   // num
            v[2 * k + 1] = mag;        // den
        }
        // 16-value bundled butterfly (16 shfl, depth 5); value vv -> lane 2*vv.
        {
            const unsigned FM = 0xffffffffu;
#pragma unroll
            for (int i = 0; i < 8; ++i) {
                float send = (lane & 16) ? v[i] : v[i + 8];
                float recv = __shfl_xor_sync(FM, send, 16);
                v[i] = ((lane & 16) ? v[i + 8] : v[i]) + recv;
            }
#pragma unroll
            for (int i = 0; i < 4; ++i) {
                float send = (lane & 8) ? v[i] : v[i + 4];
                float recv = __shfl_xor_sync(FM, send, 8);
                v[i] = ((lane & 8) ? v[i + 4] : v[i]) + recv;
            }
#pragma unroll
            for (int i = 0; i < 2; ++i) {
                float send = (lane & 4) ? v[i] : v[i + 2];
                float recv = __shfl_xor_sync(FM, send, 4);
                v[i] = ((lane & 4) ? v[i + 2] : v[i]) + recv;
            }
            {
                float send = (lane & 2) ? v[0] : v[1];
                float recv = __shfl_xor_sync(FM, send, 2);
                v[0] = ((lane & 2) ? v[1] : v[0]) + recv;
            }
            v[0] += __shfl_xor_sync(FM, v[0], 1);
            if ((lane & 1) == 0) s_wpart[wid][lane >> 1] = v[0];
        }
        __syncthreads();
        if (tid < 16) {
            float acc = 0.f;
#pragma unroll
            for (int w = 0; w < 32; ++w) acc += s_wpart[w][tid];
            g_part[blockIdx.x][tid] = acc;
        }
        __syncthreads();
        if (tid == 0) {
            __threadfence();
            asm volatile("st.global.release.gpu.b32 [%0], %1;"
                         :: "l"(&g_flags[blockIdx.x]), "r"(target) : "memory");
        }
        if (blockIdx.x == 0) {
            // block 0: wait for all flags, reduce, publish omega, release g_gen
            if (tid < NBLK) {
                unsigned w;
                do {
                    asm volatile("ld.global.acquire.gpu.b32 %0, [%1];"
                                 : "=r"(w) : "l"(&g_flags[tid]) : "memory");
                } while (w < target);
            }
            __syncthreads();
            if (tid < 512) {
                const int vv = tid >> 5;
                const float* gp = &g_part[0][0];
                float acc = __ldcg(gp + (lane      ) * 16 + vv)
                          + __ldcg(gp + (lane +  32) * 16 + vv)
                          + __ldcg(gp + (lane +  64) * 16 + vv)
                          + __ldcg(gp + (lane +  96) * 16 + vv);
#pragma unroll
                for (int o = 16; o; o >>= 1) acc += __shfl_down_sync(0xffffffffu, acc, o);
                if (lane == 0) s_red[vv] = acc;
            }
            __syncthreads();
            if (tid < K_MODES) {
                float om = s_red[2 * tid] / s_red[2 * tid + 1];
                s_omega[tid] = om;
                g_omega[target * K_MODES + tid] = om;
            }
            __syncthreads();
            if (tid == 0) {
                __threadfence();
                asm volatile("st.global.release.gpu.b32 [%0], %1;"
                             :: "l"(&g_gen), "r"(target) : "memory");
            }
        } else {
            if (tid == 0) {
                unsigned w;
                do {
                    asm volatile("ld.global.acquire.gpu.b32 %0, [%1];"
                                 : "=r"(w) : "l"(&g_gen) : "memory");
                } while (w < target);
            }
            __syncthreads();
            if (tid < K_MODES) s_omega[tid] = __ldcg(&g_omega[target * K_MODES + tid]);
            __syncthreads();
        }
    }

    const int c = e & 15;
#pragma unroll
    for (int k = 0; k < K_MODES; ++k)
        g_upos[(j * K_MODES + k) * C_CH + c] = u[k];
}

// conceptual prep value Zc[q] (q in [0,8192)) for column (k,c)
__device__ __forceinline__ float2 prep_val(int q, int k, int c) {
    float2 Hk, HM;
    if (q == 0) {
        float2 p0 = g_upos[(0 * K_MODES + k) * C_CH + c];
        float2 pL = g_upos[((HF - 1) * K_MODES + k) * C_CH + c];
        Hk = make_float2(p0.x, 0.f);
        HM = make_float2(pL.x, 0.f);
    } else {
        Hk = g_upos[(q * K_MODES + k) * C_CH + c];
        float2 pm = g_upos[((HF - q) * K_MODES + k) * C_CH + c];
        HM = make_float2(pm.x, -pm.y);
    }
    float px = Hk.x + HM.x, py = Hk.y + HM.y;
    float dx = Hk.x - HM.x, dy = Hk.y - HM.y;
    float sp, cp; sincospif((float)q * (1.0f / (float)HF), &sp, &cp);
    float qx = cp * dx - sp * dy, qy = cp * dy + sp * dx;
    return make_float2(px - qy, py + qx);
}

// Per (k,c_shifted): irfft-16384 via complex ifft-8192, slice -> u_out;
// then rfft-8192 via complex fft-4096 + untangle -> u_hat2.
__global__ __launch_bounds__(NTHR, 1) void recon_kernel(float* __restrict__ dout, int mode,
                                                        long long limf) {
    extern __shared__ float2 sh[];
    float2* sh1 = sh;             // PHI-padded 8704 float2
    float2* sh2 = sh + 8704;      // PHI-padded 4352 float2
    float*  rey = (float*)sh;     // overlays sh1 (dead by then)
    float*  imy = ((float*)sh) + 4608;
    const int b   = blockIdx.x;
    const int k   = b >> 4;
    const int c   = b & 15;
    const int tid = threadIdx.x;
    const long long lim2 = limf >> 1;

    for (int bb = tid; bb < 4096; bb += NTHR) {
        const int q0 = __brev((unsigned)bb) >> 20;
        float2 A = prep_val(q0, k, c);
        float2 B = prep_val(q0 + 4096, k, c);
        sh1[PHI(2 * bb)]     = cadd(A, B);
        sh1[PHI(2 * bb + 1)] = csub(A, B);
    }
    __syncthreads();
    r8_pass(sh1, 1024, 2,  1.f / 8.f,    +1.f);
    r8_pass(sh1, 1024, 5,  1.f / 64.f,   +1.f);
    r8_pass(sh1, 1024, 8,  1.f / 512.f,  +1.f);
    r8_pass(sh1, 1024, 11, 1.f / 4096.f, +1.f);

    const float invN = 1.0f / (float)F_LEN;
    const int cs = (c + 8) & 15;
    for (int n = tid; n < 4096; n += NTHR) {
        float2 z = sh1[PHI(2048 + n)];
        float w0 = z.x * invN, w1 = z.y * invN;
        long long i0 = (long long)(k * T_LEN + 2 * n) * C_CH + cs;
        long long i1 = i0 + C_CH;
        if (mode == MODE_C) {
            float2* o = (float2*)dout;
            if (i0 < lim2) o[i0] = make_float2(w0, 0.f);
            if (i1 < lim2) o[i1] = make_float2(w1, 0.f);
        } else {
            if (i0 < limf) dout[i0] = w0;
            if (i1 < limf) dout[i1] = w1;
        }
        sh2[PHI(__brev((unsigned)n) >> 20)] = make_float2(w0, w1);
    }
    __syncthreads();
    r8_pass(sh2, 512, 1,  1.f / 4.f,    -1.f);
    r8_pass(sh2, 512, 4,  1.f / 32.f,   -1.f);
    r8_pass(sh2, 512, 7,  1.f / 256.f,  -1.f);
    r8_pass(sh2, 512, 10, 1.f / 2048.f, -1.f);

    for (int q = tid; q < 4096; q += NTHR) {
        float2 Zk = sh2[PHI(q)];
        float2 Zm = sh2[PHI((4096 - q) & 4095)];
        float ex = 0.5f * (Zk.x + Zm.x), ey = 0.5f * (Zk.y - Zm.y);
        float bx = 0.5f * (Zk.x - Zm.x), by = 0.5f * (Zk.y + Zm.y);
        float ox = by, oy = -bx;
        float sp, cp; sincospif((float)q * (1.0f / 4096.0f), &sp, &cp);
        rey[q] = ex + cp * ox + sp * oy;
        imy[q] = ey + cp * oy - sp * ox;
        if (q == 0) { rey[4096] = Zk.x - Zk.y; imy[4096] = 0.f; }
    }
    __syncthreads();

    if (mode == MODE_R) {
        const long long base = (long long)T_LEN * K_MODES * C_CH;
        for (int t = tid; t < T_LEN; t += NTHR) {
            int bb2 = t ^ 4096;
            int rb = (bb2 <= 4096) ? bb2 : 8192 - bb2;
            long long idx = base + ((long long)t * K_MODES + k) * C_CH + c;
            if (idx < limf) dout[idx] = rey[rb];
        }
    } else {
        const long long base2 = (mode == MODE_M)
            ? (long long)(T_LEN * K_MODES * C_CH / 2)
            : (long long)(T_LEN * K_MODES * C_CH);
        float2* o = (float2*)dout;
        for (int t = tid; t < T_LEN; t += NTHR) {
            int bb2 = t ^ 4096;
            float re, im;
            if (bb2 <= 4096) { re = rey[bb2];        im = -imy[bb2]; }
            else             { re = rey[8192 - bb2]; im =  imy[8192 - bb2]; }
            long long idx = base2 + ((long long)t * K_MODES + k) * C_CH + c;
            if (idx < lim2) o[idx] = make_float2(re, im);
        }
    }
}

__global__ void omega_out_kernel(float* __restrict__ dout, int mode, long long limf) {
    int i = threadIdx.x;
    if (i >= (N_ITERS + 1) * K_MODES) return;
    if (mode == MODE_R) {
        long long idx = 2097152LL + i;
        if (idx < limf) dout[idx] = g_omega[i];
    } else {
        long long base2 = (mode == MODE_M) ? 1572864LL : 2097152LL;
        long long idx = base2 + i;
        if (idx < (limf >> 1)) ((float2*)dout)[idx] = make_float2(g_omega[i], 0.f);
    }
}

// ---------------- launch ----------------
extern "C" void kernel_launch(void* const* d_in, const int* in_sizes, int n_in,
                              void* d_out, int out_size) {
    const float* sig = (const float*)d_in[0];

    int mode;
    if (out_size == 4194624)      mode = MODE_C;
    else if (out_size == 3146048) mode = MODE_M;
    else                          mode = MODE_R;
    const long long limf = (long long)out_size;

    const int FWD_SMEM = 8704 * 8;            // 69632 B
    const int REC_SMEM = (8704 + 4352) * 8;   // 104448 B
    cudaFuncSetAttribute(fwd_fft_kernel, cudaFuncAttributeMaxDynamicSharedMemorySize, FWD_SMEM);
    cudaFuncSetAttribute(recon_kernel,   cudaFuncAttributeMaxDynamicSharedMemorySize, REC_SMEM);

    init_kernel<<<1, 256>>>();
    fwd_fft_kernel<<<C_CH, NTHR, FWD_SMEM>>>(sig);
    iterate_kernel<<<NBLK, NTHR>>>();
    recon_kernel<<<NBLK, NTHR, REC_SMEM>>>((float*)d_out, mode, limf);
    omega_out_kernel<<<1, 192>>>((float*)d_out, mode, limf);
}